// round 10
// baseline (speedup 1.0000x reference)
#include <cuda_runtime.h>
#include <cuda_bf16.h>

#define F_IN   128
#define F_OUT  64
#define N_NODES_MAX 100000

#define TILE_M        128
#define GEMM_THREADS  256
#define K_HALF        64
#define XS_STRIDE     (K_HALF + 1)   // 65: pad to kill bank conflicts

// smem: Xs[TILE_M][XS_STRIDE] + Ws[F_IN][F_OUT]  ≈ 66 KB → 3 CTAs/SM
#define SMEM_FLOATS   (TILE_M * XS_STRIDE + F_IN * F_OUT)
#define SMEM_BYTES    (SMEM_FLOATS * 4)

// scratch for support = X @ W  (25.6 MB)
__device__ float g_support[(size_t)N_NODES_MAX * F_OUT];

// packed f32x2 FMA (sm_100+; explicit 4-operand form avoids cicc ICE)
__device__ __forceinline__ void fma2(unsigned long long& d,
                                     unsigned long long a,
                                     unsigned long long b)
{
    unsigned long long r;
    asm volatile("fma.rn.f32x2 %0, %1, %2, %3;"
                 : "=l"(r) : "l"(a), "l"(b), "l"(d));
    d = r;
}
__device__ __forceinline__ unsigned long long pack2(float lo, float hi)
{
    unsigned long long r;
    asm("mov.b64 %0, {%1, %2};" : "=l"(r) : "f"(lo), "f"(hi));
    return r;
}

// ---------------------------------------------------------------------------
// Kernel 1: support = X @ W
// 128x64 tile / 256 threads; each thread: 4 rows x 8 cols (FFMA2 pairs).
// K processed in two 64-wide halves to keep smem at 66 KB (3 CTAs/SM).
// ---------------------------------------------------------------------------
__global__ void __launch_bounds__(GEMM_THREADS)
gemm_support_kernel(const float* __restrict__ X,
                    const float* __restrict__ W,
                    int n_rows)
{
    extern __shared__ float smem[];
    float* Xs = smem;                          // [TILE_M][XS_STRIDE]
    float* Ws = smem + TILE_M * XS_STRIDE;     // [F_IN][F_OUT] row-major

    const int tid      = threadIdx.x;
    const int row_base = blockIdx.x * TILE_M;

    // stage full W (8192 floats = 2048 float4; 8 per thread)
    {
        const float4* W4  = (const float4*)W;
        float4*       Ws4 = (float4*)Ws;
        #pragma unroll
        for (int i = 0; i < (F_IN * F_OUT / 4) / GEMM_THREADS; i++)
            Ws4[tid + i * GEMM_THREADS] = W4[tid + i * GEMM_THREADS];
    }

    const int tx = tid & 7;      // col group: cols tx*8 .. tx*8+7
    const int ty = tid >> 3;     // row group: rows ty*4 .. ty*4+3
    const int c0 = tx * 8;
    const int r0 = ty * 4;

    unsigned long long acc2[4][4];
    #pragma unroll
    for (int i = 0; i < 4; i++)
        #pragma unroll
        for (int j = 0; j < 4; j++)
            acc2[i][j] = 0ull;

    #pragma unroll
    for (int kb = 0; kb < 2; kb++) {
        // stage X half-tile: 128 rows x 64 cols = 2048 float4; 8 per thread
        #pragma unroll
        for (int i = 0; i < (TILE_M * K_HALF / 4) / GEMM_THREADS; i++) {
            int idx = tid + i * GEMM_THREADS;   // 0..2047
            int r   = idx >> 4;                 // /(K_HALF/4)
            int kq  = idx & 15;
            float4 v = make_float4(0.f, 0.f, 0.f, 0.f);
            int gr = row_base + r;
            if (gr < n_rows)
                v = ((const float4*)(X + (size_t)gr * F_IN))[kb * (K_HALF / 4) + kq];
            float* dstp = &Xs[r * XS_STRIDE + kq * 4];
            dstp[0] = v.x; dstp[1] = v.y; dstp[2] = v.z; dstp[3] = v.w;
        }
        __syncthreads();

        const float* wsk = Ws + kb * K_HALF * F_OUT;
        #pragma unroll 4
        for (int k = 0; k < K_HALF; k++) {
            unsigned long long xv2[4];
            #pragma unroll
            for (int i = 0; i < 4; i++) {
                float xv = Xs[(r0 + i) * XS_STRIDE + k];
                xv2[i] = pack2(xv, xv);
            }
            const unsigned long long* wrow =
                (const unsigned long long*)&wsk[k * F_OUT + c0];
            unsigned long long wv2[4];
            #pragma unroll
            for (int j = 0; j < 4; j++) wv2[j] = wrow[j];

            #pragma unroll
            for (int i = 0; i < 4; i++)
                #pragma unroll
                for (int j = 0; j < 4; j++)
                    fma2(acc2[i][j], xv2[i], wv2[j]);
        }
        __syncthreads();
    }

    // write support tile: 4 rows x 8 cols
    #pragma unroll
    for (int i = 0; i < 4; i++) {
        int gr = row_base + r0 + i;
        if (gr < n_rows) {
            float2 p0 = *(float2*)&acc2[i][0];
            float2 p1 = *(float2*)&acc2[i][1];
            float2 p2 = *(float2*)&acc2[i][2];
            float2 p3 = *(float2*)&acc2[i][3];
            float* o = g_support + (size_t)gr * F_OUT + c0;
            *(float4*)(o)     = make_float4(p0.x, p0.y, p1.x, p1.y);
            *(float4*)(o + 4) = make_float4(p2.x, p2.y, p3.x, p3.y);
        }
    }
}

// ---------------------------------------------------------------------------
// Kernel 2: out[i][c] = bias[c]
// ---------------------------------------------------------------------------
__global__ void init_out_kernel(float* __restrict__ out,
                                const float* __restrict__ bias,
                                int total)
{
    int i = blockIdx.x * blockDim.x + threadIdx.x;
    if (i < total)
        out[i] = __ldg(bias + (i & (F_OUT - 1)));
}

// ---------------------------------------------------------------------------
// Kernel 3: COO SPMM scatter-add. 16 threads per edge, float4 lanes,
// red.global.add.v4.f32 (no return trip). Two independent edges per thread.
// ---------------------------------------------------------------------------
__global__ void spmm_scatter_kernel(const float* __restrict__ ew,
                                    const int*  __restrict__ src,
                                    const int*  __restrict__ dst,
                                    float* __restrict__ out,
                                    int E, int half)
{
    long long t = (long long)blockIdx.x * blockDim.x + threadIdx.x;
    int e0 = (int)(t >> 4);
    int q  = (int)(t & 15);
    if (e0 >= half) return;
    int e1 = e0 + half;
    bool has1 = (e1 < E);

    int   s0 = __ldg(src + e0);
    int   d0 = __ldg(dst + e0);
    float w0 = __ldg(ew  + e0);
    int   s1 = 0, d1 = 0;
    float w1 = 0.f;
    if (has1) {
        s1 = __ldg(src + e1);
        d1 = __ldg(dst + e1);
        w1 = __ldg(ew  + e1);
    }

    const float4 v0 = *(const float4*)(g_support + (size_t)s0 * F_OUT + q * 4);
    float4 v1 = make_float4(0.f, 0.f, 0.f, 0.f);
    if (has1)
        v1 = *(const float4*)(g_support + (size_t)s1 * F_OUT + q * 4);

    {
        float* p = out + (size_t)d0 * F_OUT + q * 4;
        float m0 = v0.x * w0, m1 = v0.y * w0, m2 = v0.z * w0, m3 = v0.w * w0;
        asm volatile("red.global.add.v4.f32 [%0], {%1, %2, %3, %4};"
                     :: "l"(p), "f"(m0), "f"(m1), "f"(m2), "f"(m3)
                     : "memory");
    }
    if (has1) {
        float* p = out + (size_t)d1 * F_OUT + q * 4;
        float m0 = v1.x * w1, m1 = v1.y * w1, m2 = v1.z * w1, m3 = v1.w * w1;
        asm volatile("red.global.add.v4.f32 [%0], {%1, %2, %3, %4};"
                     :: "l"(p), "f"(m0), "f"(m1), "f"(m2), "f"(m3)
                     : "memory");
    }
}

// ---------------------------------------------------------------------------
extern "C" void kernel_launch(void* const* d_in, const int* in_sizes, int n_in,
                              void* d_out, int out_size)
{
    const float* x    = (const float*)d_in[0];   // [N, 128]
    const float* ew   = (const float*)d_in[1];   // [E]
    const float* W    = (const float*)d_in[2];   // [128, 64]
    const float* bias = (const float*)d_in[3];   // [64]
    const int*   src  = (const int*)  d_in[4];   // [E]
    const int*   dst  = (const int*)  d_in[5];   // [E]
    float*       out  = (float*)d_out;           // [N, 64]

    const int n = in_sizes[0] / F_IN;
    const int E = in_sizes[1];

    cudaFuncSetAttribute(gemm_support_kernel,
                         cudaFuncAttributeMaxDynamicSharedMemorySize, SMEM_BYTES);

    const int gemm_blocks = (n + TILE_M - 1) / TILE_M;
    gemm_support_kernel<<<gemm_blocks, GEMM_THREADS, SMEM_BYTES>>>(x, W, n);

    const int total = n * F_OUT;
    init_out_kernel<<<(total + 255) / 256, 256>>>(out, bias, total);

    const int half = (E + 1) / 2;
    const long long spmm_threads = (long long)half * 16;
    const int spmm_blocks = (int)((spmm_threads + 255) / 256);
    spmm_scatter_kernel<<<spmm_blocks, 256>>>(ew, src, dst, out, E, half);
}

// round 12
// speedup vs baseline: 1.2296x; 1.2296x over previous
#include <cuda_runtime.h>
#include <cuda_fp16.h>
#include <cuda_bf16.h>

#define F_IN   128
#define F_OUT  64
#define N_NODES_MAX 100000

#define TILE_M        128
#define GEMM_THREADS  128
#define K_HALF        64
#define XS_STRIDE     (K_HALF + 1)   // 65: pad to kill bank conflicts

// smem: Xs[128][65] + Ws_half[64][64] = 12416 floats = 49.7 KB -> 4 CTAs/SM
#define SMEM_FLOATS   (TILE_M * XS_STRIDE + K_HALF * F_OUT)
#define SMEM_BYTES    (SMEM_FLOATS * 4)

// scratch: support = X @ W stored as fp16 (12.8 MB) to halve gather traffic
__device__ __half g_support_h[(size_t)N_NODES_MAX * F_OUT];

// packed f32x2 FMA (sm_100+; explicit 4-operand form avoids cicc ICE)
__device__ __forceinline__ void fma2(unsigned long long& d,
                                     unsigned long long a,
                                     unsigned long long b)
{
    unsigned long long r;
    asm volatile("fma.rn.f32x2 %0, %1, %2, %3;"
                 : "=l"(r) : "l"(a), "l"(b), "l"(d));
    d = r;
}
__device__ __forceinline__ unsigned long long pack2(float lo, float hi)
{
    unsigned long long r;
    asm("mov.b64 %0, {%1, %2};" : "=l"(r) : "f"(lo), "f"(hi));
    return r;
}

// ---------------------------------------------------------------------------
// Kernel 1: support = X @ W  (fp32 compute, fp16 store)
// 128x64 tile / 128 threads; 8x8 per thread (FFMA2 pairs).
// K split into two 64-wide passes; only the active W half is staged.
// ---------------------------------------------------------------------------
__global__ void __launch_bounds__(GEMM_THREADS)
gemm_support_kernel(const float* __restrict__ X,
                    const float* __restrict__ W,
                    int n_rows)
{
    extern __shared__ float smem[];
    float* Xs = smem;                          // [TILE_M][XS_STRIDE]
    float* Ws = smem + TILE_M * XS_STRIDE;     // [K_HALF][F_OUT]

    const int tid      = threadIdx.x;
    const int row_base = blockIdx.x * TILE_M;

    const int tx = tid & 7;      // col group: cols tx*8 .. tx*8+7
    const int ty = tid >> 3;     // row group: rows ty*8 .. ty*8+7
    const int c0 = tx * 8;
    const int r0 = ty * 8;

    unsigned long long acc2[8][4];
    #pragma unroll
    for (int i = 0; i < 8; i++)
        #pragma unroll
        for (int j = 0; j < 4; j++)
            acc2[i][j] = 0ull;

    #pragma unroll
    for (int kb = 0; kb < 2; kb++) {
        // stage W half: 64x64 = 1024 float4; 8 per thread
        {
            const float4* W4  = (const float4*)(W + kb * K_HALF * F_OUT);
            float4*       Ws4 = (float4*)Ws;
            #pragma unroll
            for (int i = 0; i < (K_HALF * F_OUT / 4) / GEMM_THREADS; i++)
                Ws4[tid + i * GEMM_THREADS] = W4[tid + i * GEMM_THREADS];
        }
        // stage X half-tile: 128 rows x 64 cols = 2048 float4; 16 per thread
        #pragma unroll
        for (int i = 0; i < (TILE_M * K_HALF / 4) / GEMM_THREADS; i++) {
            int idx = tid + i * GEMM_THREADS;   // 0..2047
            int r   = idx >> 4;                 // /(K_HALF/4)
            int kq  = idx & 15;
            float4 v = make_float4(0.f, 0.f, 0.f, 0.f);
            int gr = row_base + r;
            if (gr < n_rows)
                v = ((const float4*)(X + (size_t)gr * F_IN))[kb * (K_HALF / 4) + kq];
            float* dstp = &Xs[r * XS_STRIDE + kq * 4];
            dstp[0] = v.x; dstp[1] = v.y; dstp[2] = v.z; dstp[3] = v.w;
        }
        __syncthreads();

        #pragma unroll 4
        for (int k = 0; k < K_HALF; k++) {
            unsigned long long xv2[8];
            #pragma unroll
            for (int i = 0; i < 8; i++) {
                float xv = Xs[(r0 + i) * XS_STRIDE + k];
                xv2[i] = pack2(xv, xv);
            }
            const unsigned long long* wrow =
                (const unsigned long long*)&Ws[k * F_OUT + c0];
            unsigned long long wv2[4];
            #pragma unroll
            for (int j = 0; j < 4; j++) wv2[j] = wrow[j];

            #pragma unroll
            for (int i = 0; i < 8; i++)
                #pragma unroll
                for (int j = 0; j < 4; j++)
                    fma2(acc2[i][j], xv2[i], wv2[j]);
        }
        __syncthreads();
    }

    // write support tile as fp16: 8 rows x 8 cols (16B per row)
    #pragma unroll
    for (int i = 0; i < 8; i++) {
        int gr = row_base + r0 + i;
        if (gr < n_rows) {
            float2 p0 = *(float2*)&acc2[i][0];
            float2 p1 = *(float2*)&acc2[i][1];
            float2 p2 = *(float2*)&acc2[i][2];
            float2 p3 = *(float2*)&acc2[i][3];
            __half2 h0 = __float22half2_rn(p0);
            __half2 h1 = __float22half2_rn(p1);
            __half2 h2 = __float22half2_rn(p2);
            __half2 h3 = __float22half2_rn(p3);
            uint4 packed = make_uint4(*(unsigned*)&h0, *(unsigned*)&h1,
                                      *(unsigned*)&h2, *(unsigned*)&h3);
            *(uint4*)(g_support_h + (size_t)gr * F_OUT + c0) = packed;
        }
    }
}

// ---------------------------------------------------------------------------
// Kernel 2: out[i][c] = bias[c]
// ---------------------------------------------------------------------------
__global__ void init_out_kernel(float* __restrict__ out,
                                const float* __restrict__ bias,
                                int total)
{
    int i = blockIdx.x * blockDim.x + threadIdx.x;
    if (i < total)
        out[i] = __ldg(bias + (i & (F_OUT - 1)));
}

// ---------------------------------------------------------------------------
// Kernel 3: COO SPMM scatter-add. 16 threads per edge; each lane reads
// 4 fp16 support values (8B), converts to fp32, red.global.add.v4.f32.
// Two independent edges per thread for MLP.
// ---------------------------------------------------------------------------
__global__ void spmm_scatter_kernel(const float* __restrict__ ew,
                                    const int*  __restrict__ src,
                                    const int*  __restrict__ dst,
                                    float* __restrict__ out,
                                    int E, int half)
{
    long long t = (long long)blockIdx.x * blockDim.x + threadIdx.x;
    int e0 = (int)(t >> 4);
    int q  = (int)(t & 15);
    if (e0 >= half) return;
    int e1 = e0 + half;
    bool has1 = (e1 < E);

    int   s0 = __ldg(src + e0);
    int   d0 = __ldg(dst + e0);
    float w0 = __ldg(ew  + e0);
    int   s1 = 0, d1 = 0;
    float w1 = 0.f;
    if (has1) {
        s1 = __ldg(src + e1);
        d1 = __ldg(dst + e1);
        w1 = __ldg(ew  + e1);
    }

    // two independent 8B fp16 reads in flight
    uint2 raw0 = *(const uint2*)(g_support_h + (size_t)s0 * F_OUT + q * 4);
    uint2 raw1 = make_uint2(0u, 0u);
    if (has1)
        raw1 = *(const uint2*)(g_support_h + (size_t)s1 * F_OUT + q * 4);

    {
        float2 a = __half22float2(*(__half2*)&raw0.x);
        float2 b = __half22float2(*(__half2*)&raw0.y);
        float* p = out + (size_t)d0 * F_OUT + q * 4;
        float m0 = a.x * w0, m1 = a.y * w0, m2 = b.x * w0, m3 = b.y * w0;
        asm volatile("red.global.add.v4.f32 [%0], {%1, %2, %3, %4};"
                     :: "l"(p), "f"(m0), "f"(m1), "f"(m2), "f"(m3)
                     : "memory");
    }
    if (has1) {
        float2 a = __half22float2(*(__half2*)&raw1.x);
        float2 b = __half22float2(*(__half2*)&raw1.y);
        float* p = out + (size_t)d1 * F_OUT + q * 4;
        float m0 = a.x * w1, m1 = a.y * w1, m2 = b.x * w1, m3 = b.y * w1;
        asm volatile("red.global.add.v4.f32 [%0], {%1, %2, %3, %4};"
                     :: "l"(p), "f"(m0), "f"(m1), "f"(m2), "f"(m3)
                     : "memory");
    }
}

// ---------------------------------------------------------------------------
extern "C" void kernel_launch(void* const* d_in, const int* in_sizes, int n_in,
                              void* d_out, int out_size)
{
    const float* x    = (const float*)d_in[0];   // [N, 128]
    const float* ew   = (const float*)d_in[1];   // [E]
    const float* W    = (const float*)d_in[2];   // [128, 64]
    const float* bias = (const float*)d_in[3];   // [64]
    const int*   src  = (const int*)  d_in[4];   // [E]
    const int*   dst  = (const int*)  d_in[5];   // [E]
    float*       out  = (float*)d_out;           // [N, 64]

    const int n = in_sizes[0] / F_IN;
    const int E = in_sizes[1];

    cudaFuncSetAttribute(gemm_support_kernel,
                         cudaFuncAttributeMaxDynamicSharedMemorySize, SMEM_BYTES);

    const int gemm_blocks = (n + TILE_M - 1) / TILE_M;
    gemm_support_kernel<<<gemm_blocks, GEMM_THREADS, SMEM_BYTES>>>(x, W, n);

    const int total = n * F_OUT;
    init_out_kernel<<<(total + 255) / 256, 256>>>(out, bias, total);

    const int half = (E + 1) / 2;
    const long long spmm_threads = (long long)half * 16;
    const int spmm_blocks = (int)((spmm_threads + 255) / 256);
    spmm_scatter_kernel<<<spmm_blocks, 256>>>(ew, src, dst, out, E, half);
}

// round 17
// speedup vs baseline: 1.3253x; 1.0778x over previous
#include <cuda_runtime.h>
#include <cuda_fp16.h>
#include <cuda_bf16.h>

#define F_IN   128
#define F_OUT  64
#define N_NODES_MAX 100000

#define TILE_M        128
#define GEMM_THREADS  128
#define K_HALF        64
#define XS_STRIDE     (K_HALF + 1)   // 65: pad to kill bank conflicts

// smem: Xs[128][65] + Ws_half[64][64] = 12416 floats = 49.7 KB -> 4 CTAs/SM
#define SMEM_FLOATS   (TILE_M * XS_STRIDE + K_HALF * F_OUT)
#define SMEM_BYTES    (SMEM_FLOATS * 4)

// scratch: support = X @ W stored as fp16 (12.8 MB) to halve gather traffic
__device__ __half g_support_h[(size_t)N_NODES_MAX * F_OUT];

// packed f32x2 FMA (sm_100+; explicit 4-operand form avoids cicc ICE)
__device__ __forceinline__ void fma2(unsigned long long& d,
                                     unsigned long long a,
                                     unsigned long long b)
{
    unsigned long long r;
    asm volatile("fma.rn.f32x2 %0, %1, %2, %3;"
                 : "=l"(r) : "l"(a), "l"(b), "l"(d));
    d = r;
}
__device__ __forceinline__ unsigned long long pack2(float lo, float hi)
{
    unsigned long long r;
    asm("mov.b64 %0, {%1, %2};" : "=l"(r) : "f"(lo), "f"(hi));
    return r;
}

// ---------------------------------------------------------------------------
// Kernel 1: support = X @ W (fp32 compute, fp16 store) + out rows = bias.
// 128x64 tile / 128 threads; 8x8 per thread (FFMA2 pairs).
// K split into two 64-wide passes; only the active W half is staged.
// __launch_bounds__(128,4): cap regs at 124 so 4 CTAs/SM are resident.
// ---------------------------------------------------------------------------
__global__ void __launch_bounds__(GEMM_THREADS, 4)
gemm_support_kernel(const float* __restrict__ X,
                    const float* __restrict__ W,
                    const float* __restrict__ bias,
                    float* __restrict__ out,
                    int n_rows)
{
    extern __shared__ float smem[];
    float* Xs = smem;                          // [TILE_M][XS_STRIDE]
    float* Ws = smem + TILE_M * XS_STRIDE;     // [K_HALF][F_OUT]

    const int tid      = threadIdx.x;
    const int row_base = blockIdx.x * TILE_M;

    // bias-init for this CTA's 128 out rows.
    // 128 rows x 16 float4 chunks (F_OUT=64 floats) = 2048 chunks, 16/thread.
    // Bias chunk index == row chunk index c (0..15).
    {
        const float4* bias4 = (const float4*)bias;
        #pragma unroll
        for (int i = 0; i < 16; i++) {
            int idx = tid + i * GEMM_THREADS;   // 0..2047
            int r   = idx >> 4;                 // row 0..127
            int c   = idx & 15;                 // float4 chunk 0..15
            int gr  = row_base + r;
            if (gr < n_rows)
                ((float4*)(out + (size_t)gr * F_OUT))[c] = bias4[c];
        }
    }

    const int tx = tid & 7;      // col group: cols tx*8 .. tx*8+7
    const int ty = tid >> 3;     // row group: rows ty*8 .. ty*8+7
    const int c0 = tx * 8;
    const int r0 = ty * 8;

    unsigned long long acc2[8][4];
    #pragma unroll
    for (int i = 0; i < 8; i++)
        #pragma unroll
        for (int j = 0; j < 4; j++)
            acc2[i][j] = 0ull;

    #pragma unroll
    for (int kb = 0; kb < 2; kb++) {
        if (kb > 0) __syncthreads();   // protect Ws/Xs reuse
        // stage W half: 64x64 = 1024 float4; 8 per thread
        {
            const float4* W4  = (const float4*)(W + kb * K_HALF * F_OUT);
            float4*       Ws4 = (float4*)Ws;
            #pragma unroll
            for (int i = 0; i < (K_HALF * F_OUT / 4) / GEMM_THREADS; i++)
                Ws4[tid + i * GEMM_THREADS] = W4[tid + i * GEMM_THREADS];
        }
        // stage X half-tile: 128 rows x 64 cols = 2048 float4; 16 per thread
        #pragma unroll
        for (int i = 0; i < (TILE_M * K_HALF / 4) / GEMM_THREADS; i++) {
            int idx = tid + i * GEMM_THREADS;   // 0..2047
            int r   = idx >> 4;                 // /(K_HALF/4)
            int kq  = idx & 15;
            float4 v = make_float4(0.f, 0.f, 0.f, 0.f);
            int gr = row_base + r;
            if (gr < n_rows)
                v = ((const float4*)(X + (size_t)gr * F_IN))[kb * (K_HALF / 4) + kq];
            float* dstp = &Xs[r * XS_STRIDE + kq * 4];
            dstp[0] = v.x; dstp[1] = v.y; dstp[2] = v.z; dstp[3] = v.w;
        }
        __syncthreads();

        #pragma unroll 2
        for (int k = 0; k < K_HALF; k++) {
            unsigned long long xv2[8];
            #pragma unroll
            for (int i = 0; i < 8; i++) {
                float xv = Xs[(r0 + i) * XS_STRIDE + k];
                xv2[i] = pack2(xv, xv);
            }
            const unsigned long long* wrow =
                (const unsigned long long*)&Ws[k * F_OUT + c0];
            unsigned long long wv2[4];
            #pragma unroll
            for (int j = 0; j < 4; j++) wv2[j] = wrow[j];

            #pragma unroll
            for (int i = 0; i < 8; i++)
                #pragma unroll
                for (int j = 0; j < 4; j++)
                    fma2(acc2[i][j], xv2[i], wv2[j]);
        }
    }

    // write support tile as fp16: 8 rows x 8 cols (16B per row)
    #pragma unroll
    for (int i = 0; i < 8; i++) {
        int gr = row_base + r0 + i;
        if (gr < n_rows) {
            float2 p0 = *(float2*)&acc2[i][0];
            float2 p1 = *(float2*)&acc2[i][1];
            float2 p2 = *(float2*)&acc2[i][2];
            float2 p3 = *(float2*)&acc2[i][3];
            __half2 h0 = __float22half2_rn(p0);
            __half2 h1 = __float22half2_rn(p1);
            __half2 h2 = __float22half2_rn(p2);
            __half2 h3 = __float22half2_rn(p3);
            uint4 packed = make_uint4(*(unsigned*)&h0, *(unsigned*)&h1,
                                      *(unsigned*)&h2, *(unsigned*)&h3);
            *(uint4*)(g_support_h + (size_t)gr * F_OUT + c0) = packed;
        }
    }
}

// ---------------------------------------------------------------------------
// Kernel 2: COO SPMM scatter-add. 16 threads per edge; each lane reads
// 4 fp16 support values (8B), converts to fp32, red.global.add.v4.f32.
// Two independent edges per thread for MLP.
// ---------------------------------------------------------------------------
__global__ void spmm_scatter_kernel(const float* __restrict__ ew,
                                    const int*  __restrict__ src,
                                    const int*  __restrict__ dst,
                                    float* __restrict__ out,
                                    int E, int half)
{
    long long t = (long long)blockIdx.x * blockDim.x + threadIdx.x;
    int e0 = (int)(t >> 4);
    int q  = (int)(t & 15);
    if (e0 >= half) return;
    int e1 = e0 + half;
    bool has1 = (e1 < E);

    int   s0 = __ldg(src + e0);
    int   d0 = __ldg(dst + e0);
    float w0 = __ldg(ew  + e0);
    int   s1 = 0, d1 = 0;
    float w1 = 0.f;
    if (has1) {
        s1 = __ldg(src + e1);
        d1 = __ldg(dst + e1);
        w1 = __ldg(ew  + e1);
    }

    // two independent 8B fp16 reads in flight
    uint2 raw0 = *(const uint2*)(g_support_h + (size_t)s0 * F_OUT + q * 4);
    uint2 raw1 = make_uint2(0u, 0u);
    if (has1)
        raw1 = *(const uint2*)(g_support_h + (size_t)s1 * F_OUT + q * 4);

    {
        float2 a = __half22float2(*(__half2*)&raw0.x);
        float2 b = __half22float2(*(__half2*)&raw0.y);
        float* p = out + (size_t)d0 * F_OUT + q * 4;
        float m0 = a.x * w0, m1 = a.y * w0, m2 = b.x * w0, m3 = b.y * w0;
        asm volatile("red.global.add.v4.f32 [%0], {%1, %2, %3, %4};"
                     :: "l"(p), "f"(m0), "f"(m1), "f"(m2), "f"(m3)
                     : "memory");
    }
    if (has1) {
        float2 a = __half22float2(*(__half2*)&raw1.x);
        float2 b = __half22float2(*(__half2*)&raw1.y);
        float* p = out + (size_t)d1 * F_OUT + q * 4;
        float m0 = a.x * w1, m1 = a.y * w1, m2 = b.x * w1, m3 = b.y * w1;
        asm volatile("red.global.add.v4.f32 [%0], {%1, %2, %3, %4};"
                     :: "l"(p), "f"(m0), "f"(m1), "f"(m2), "f"(m3)
                     : "memory");
    }
}

// ---------------------------------------------------------------------------
extern "C" void kernel_launch(void* const* d_in, const int* in_sizes, int n_in,
                              void* d_out, int out_size)
{
    const float* x    = (const float*)d_in[0];   // [N, 128]
    const float* ew   = (const float*)d_in[1];   // [E]
    const float* W    = (const float*)d_in[2];   // [128, 64]
    const float* bias = (const float*)d_in[3];   // [64]
    const int*   src  = (const int*)  d_in[4];   // [E]
    const int*   dst  = (const int*)  d_in[5];   // [E]
    float*       out  = (float*)d_out;           // [N, 64]

    const int n = in_sizes[0] / F_IN;
    const int E = in_sizes[1];

    cudaFuncSetAttribute(gemm_support_kernel,
                         cudaFuncAttributeMaxDynamicSharedMemorySize, SMEM_BYTES);

    const int gemm_blocks = (n + TILE_M - 1) / TILE_M;
    gemm_support_kernel<<<gemm_blocks, GEMM_THREADS, SMEM_BYTES>>>(x, W, bias, out, n);

    const int half = (E + 1) / 2;
    const long long spmm_threads = (long long)half * 16;
    const int spmm_blocks = (int)((spmm_threads + 255) / 256);
    spmm_scatter_kernel<<<spmm_blocks, 256>>>(ew, src, dst, out, E, half);
}